// round 5
// baseline (speedup 1.0000x reference)
#include <cuda_runtime.h>
#include <cuda_fp16.h>
#include <cstdint>

// ============================================================================
// ModulatedConv1d (B=16, C=512, L=2048, K=3, pad=1) — plain sm_100 path
//   s[b,i]    = MOD_SCALE * style[b,:] @ modW[i,:] + bias[i]
//   gain[b,o] = SCALE * rsqrt(SCALE^2 * sum_i s^2 * wsq[o,i] + 1e-8)
//   out[b,o,l]= gain[b,o] * sum_{i,k} W[o,i,k] * s[b,i] * x[b,i,l+k-1]
// Pre-pass builds x_t[b][l][i] = fp16(s*x); main GEMM = mma.m16n8k16 f16->f32.
// CTA tile 128(o) x 256(l), 512 threads, 4-stage cp.async pipeline, ldmatrix.
// ============================================================================

#define MOD_SCALE_F 0.04419417382415922f   /* 1/sqrt(512)   */
#define SCALE_F     0.014731391274719739f  /* 1/sqrt(512*9) */

#define NTHREADS 512
// Stage layout: A = 3 taps x 128 rows x 80B = 30720; X = 258 rows x 80B = 20640
#define A_TAP 10240
#define X_OFF 30720
#define STAGE 51360
#define NSTAGE 4
#define SMEM_TOTAL (NSTAGE * STAGE)   /* 205440 */

// static device scratch (no runtime allocation)
__device__ float  g_s[16 * 512];
__device__ float  g_wsq[512 * 512];
__device__ float  g_gain[16 * 512];
__device__ __half g_wh[3 * 512 * 512];        // [k][o][i], fp16
__device__ __half g_xt[16 * 2048 * 512];      // [b][l][i] = fp16(s*x)

// ---------------------------------------------------------------------------
__device__ __forceinline__ uint32_t smem_u32(const void* p) {
    uint32_t a;
    asm("{ .reg .u64 t; cvta.to.shared.u64 t, %1; cvt.u32.u64 %0, t; }" : "=r"(a) : "l"(p));
    return a;
}
__device__ __forceinline__ void cp16(uint32_t dst, const void* src) {
    asm volatile("cp.async.cg.shared.global [%0], [%1], 16;" :: "r"(dst), "l"(src));
}
__device__ __forceinline__ void cp16z(uint32_t dst, const void* src, int szcp) {
    asm volatile("cp.async.cg.shared.global [%0], [%1], 16, %2;" :: "r"(dst), "l"(src), "r"(szcp));
}
__device__ __forceinline__ void ldsm4(uint32_t* r, uint32_t addr) {
    asm volatile("ldmatrix.sync.aligned.m8n8.x4.shared.b16 {%0,%1,%2,%3}, [%4];"
        : "=r"(r[0]), "=r"(r[1]), "=r"(r[2]), "=r"(r[3]) : "r"(addr));
}
__device__ __forceinline__ void mma_f16(float* c, const uint32_t* a, uint32_t b0, uint32_t b1) {
    asm volatile(
        "mma.sync.aligned.m16n8k16.row.col.f32.f16.f16.f32 "
        "{%0,%1,%2,%3}, {%4,%5,%6,%7}, {%8,%9}, {%0,%1,%2,%3};"
        : "+f"(c[0]), "+f"(c[1]), "+f"(c[2]), "+f"(c[3])
        : "r"(a[0]), "r"(a[1]), "r"(a[2]), "r"(a[3]), "r"(b0), "r"(b1));
}

// ---------------------------------------------------------------------------
// Prep kernels
// ---------------------------------------------------------------------------
__global__ void prep_w(const float* __restrict__ w) {
    int idx = blockIdx.x * 256 + threadIdx.x;  // idx = o*512 + i, grid 1024
    float w0 = w[idx * 3 + 0];
    float w1 = w[idx * 3 + 1];
    float w2 = w[idx * 3 + 2];
    g_wh[0 * 262144 + idx] = __float2half_rn(w0);
    g_wh[1 * 262144 + idx] = __float2half_rn(w1);
    g_wh[2 * 262144 + idx] = __float2half_rn(w2);
    g_wsq[idx] = w0 * w0 + w1 * w1 + w2 * w2;
}

__global__ void prep_s(const float* __restrict__ style, const float* __restrict__ modw,
                       const float* __restrict__ bias) {
    __shared__ float st[512];
    int b = blockIdx.x, chunk = blockIdx.y;  // grid (16, 8)
    for (int i = threadIdx.x; i < 512; i += 256) st[i] = style[b * 512 + i];
    __syncthreads();
    int warp = threadIdx.x >> 5, lane = threadIdx.x & 31;
    for (int it = 0; it < 8; it++) {
        int i = chunk * 64 + it * 8 + warp;
        const float* mrow = modw + (size_t)i * 512;
        float acc = 0.f;
        #pragma unroll
        for (int t = 0; t < 16; t++) acc += mrow[lane + t * 32] * st[lane + t * 32];
        #pragma unroll
        for (int o = 16; o; o >>= 1) acc += __shfl_xor_sync(0xFFFFFFFFu, acc, o);
        if (lane == 0) g_s[b * 512 + i] = acc * MOD_SCALE_F + bias[i];
    }
}

__global__ void prep_gain() {
    __shared__ float s2[512];
    int b = blockIdx.x, chunk = blockIdx.y;  // grid (16, 8)
    for (int i = threadIdx.x; i < 512; i += 256) {
        float v = g_s[b * 512 + i];
        s2[i] = v * v;
    }
    __syncthreads();
    int warp = threadIdx.x >> 5, lane = threadIdx.x & 31;
    for (int it = 0; it < 8; it++) {
        int o = chunk * 64 + it * 8 + warp;
        const float* wr = g_wsq + (size_t)o * 512;
        float acc = 0.f;
        #pragma unroll
        for (int t = 0; t < 16; t++) acc += wr[lane + t * 32] * s2[lane + t * 32];
        #pragma unroll
        for (int off = 16; off; off >>= 1) acc += __shfl_xor_sync(0xFFFFFFFFu, acc, off);
        if (lane == 0)
            g_gain[b * 512 + o] = SCALE_F * rsqrtf(SCALE_F * SCALE_F * acc + 1e-8f);
    }
}

// Transpose + scale + fp16: x[b][i][l] -> x_t[b][l][i], tile 64(i) x 32(l)
__global__ void prep_xt(const float* __restrict__ x) {
    __shared__ float sm[64][33];
    const int lt = blockIdx.x;   // 0..63
    const int it = blockIdx.y;   // 0..7
    const int b  = blockIdx.z;   // 0..15
    const int warp = threadIdx.x >> 5, lane = threadIdx.x & 31;
    const int l0 = lt * 32, i0 = it * 64;
    const float* xb = x + ((size_t)b * 512) * 2048;

    #pragma unroll
    for (int r = 0; r < 8; r++) {
        int il = warp * 8 + r;
        float sv = g_s[b * 512 + i0 + il];
        sm[il][lane] = xb[(size_t)(i0 + il) * 2048 + l0 + lane] * sv;
    }
    __syncthreads();
    #pragma unroll
    for (int rr = 0; rr < 4; rr++) {
        int ll = warp * 4 + rr;
        __half2 h = __floats2half2_rn(sm[lane * 2][ll], sm[lane * 2 + 1][ll]);
        *(__half2*)(g_xt + (((size_t)b * 2048) + (l0 + ll)) * 512 + i0 + lane * 2) = h;
    }
}

// ---------------------------------------------------------------------------
// Main kernel: 512 CTAs = 4 o x 8 l x 16 b; 512 threads (16 warps, 4m x 4n)
// warp tile 32(o) x 64(l); 16 K-chunks of 32 i x 3 taps; 4-stage pipeline.
// ---------------------------------------------------------------------------
__global__ void __launch_bounds__(NTHREADS, 1)
conv_main(float* __restrict__ out) {
    extern __shared__ char smem[];
    const uint32_t sb = smem_u32(smem);

    const int tid  = threadIdx.x;
    const int warp = tid >> 5;
    const int lane = tid & 31;
    const int mw = (warp & 3) * 32;
    const int nw = (warp >> 2) * 64;

    const int bx    = blockIdx.x;
    const int obase = (bx & 3) * 128;
    const int l0    = ((bx >> 2) & 7) * 256;
    const int b     = bx >> 5;

    // per-lane ldmatrix address components
    const uint32_t aoff = (uint32_t)(mw + (lane & 15)) * 80 + ((lane & 16) ? 16u : 0u);
    const uint32_t boff = X_OFF + (uint32_t)(nw + (lane & 7) + ((lane >> 4) << 3)) * 80
                        + ((lane & 8) ? 16u : 0u);

    const __half* xt = g_xt + ((size_t)b * 2048) * 512;
    const __half* wh = g_wh + (size_t)obase * 512;

    float acc[2][8][4];
    #pragma unroll
    for (int mi = 0; mi < 2; mi++)
        #pragma unroll
        for (int ni = 0; ni < 8; ni++)
            #pragma unroll
            for (int j = 0; j < 4; j++) acc[mi][ni][j] = 0.f;

    // ---- cp.async stage loader: one commit group per chunk ----
    auto issue = [&](int ic) {
        uint32_t base = sb + (uint32_t)(ic & (NSTAGE - 1)) * STAGE;
        // A: 3 taps x 128 rows x 4x16B = 1536 ops (3 per thread)
        {
            int o = tid >> 2, c = tid & 3;
            const __half* s0 = wh + (size_t)o * 512 + ic * 32 + c * 8;
            uint32_t d = base + o * 80 + c * 16;
            cp16(d,             s0);
            cp16(d + A_TAP,     s0 + 262144);
            cp16(d + 2 * A_TAP, s0 + 2 * 262144);
        }
        // X: 258 rows x 4x16B = 1032 ops (rows l0-1 .. l0+256)
        for (int idx = tid; idx < 1032; idx += NTHREADS) {
            int row = idx >> 2, c = idx & 3;
            int l = l0 - 1 + row;
            int ok = (l >= 0 && l < 2048) ? 16 : 0;
            const __half* s1 = xt + (size_t)l * 512 + ic * 32 + c * 8;
            cp16z(base + X_OFF + row * 80 + c * 16, s1, ok);
        }
        asm volatile("cp.async.commit_group;");
    };

    issue(0);
    issue(1);
    issue(2);

    for (int ic = 0; ic < 16; ic++) {
        asm volatile("cp.async.wait_group 2;" ::: "memory");
        __syncthreads();

        const uint32_t base  = sb + (uint32_t)(ic & (NSTAGE - 1)) * STAGE;
        const uint32_t abase = base + aoff;
        const uint32_t bbase = base + boff;

        #pragma unroll
        for (int t = 0; t < 3; t++) {
            #pragma unroll
            for (int ks = 0; ks < 2; ks++) {
                uint32_t a0[4], a1[4];
                ldsm4(a0, abase + t * A_TAP + ks * 32);
                ldsm4(a1, abase + t * A_TAP + 16 * 80 + ks * 32);
                #pragma unroll
                for (int np = 0; np < 4; np++) {
                    uint32_t bf[4];
                    ldsm4(bf, bbase + (np * 16 + t) * 80 + ks * 32);
                    mma_f16(acc[0][np * 2],     a0, bf[0], bf[1]);
                    mma_f16(acc[1][np * 2],     a1, bf[0], bf[1]);
                    mma_f16(acc[0][np * 2 + 1], a0, bf[2], bf[3]);
                    mma_f16(acc[1][np * 2 + 1], a1, bf[2], bf[3]);
                }
            }
        }

        if (ic < 13) issue(ic + 3);
    }

    // ---- epilogue: apply gain, store ----
    {
        const int r0 = obase + mw + (lane >> 2);
        const float g00 = g_gain[b * 512 + r0];
        const float g01 = g_gain[b * 512 + r0 + 8];
        const float g10 = g_gain[b * 512 + r0 + 16];
        const float g11 = g_gain[b * 512 + r0 + 24];
        const int lcol = l0 + nw + (lane & 3) * 2;

        #pragma unroll
        for (int mi = 0; mi < 2; mi++) {
            const int ra = r0 + mi * 16;
            const float ga = mi ? g10 : g00;
            const float gb = mi ? g11 : g01;
            float* outa = out + ((size_t)(b * 512 + ra)) * 2048 + lcol;
            float* outb = out + ((size_t)(b * 512 + ra + 8)) * 2048 + lcol;
            #pragma unroll
            for (int ni = 0; ni < 8; ni++) {
                float2 va, vb;
                va.x = acc[mi][ni][0] * ga;
                va.y = acc[mi][ni][1] * ga;
                vb.x = acc[mi][ni][2] * gb;
                vb.y = acc[mi][ni][3] * gb;
                *(float2*)(outa + ni * 8) = va;
                *(float2*)(outb + ni * 8) = vb;
            }
        }
    }
}

// ---------------------------------------------------------------------------
extern "C" void kernel_launch(void* const* d_in, const int* in_sizes, int n_in,
                              void* d_out, int out_size) {
    const float* x      = (const float*)d_in[0];
    const float* style  = (const float*)d_in[1];
    const float* weight = (const float*)d_in[2];
    const float* modw   = (const float*)d_in[3];
    const float* bias   = (const float*)d_in[4];
    float* out = (float*)d_out;

    cudaFuncSetAttribute(conv_main, cudaFuncAttributeMaxDynamicSharedMemorySize, SMEM_TOTAL);

    prep_s<<<dim3(16, 8), 256>>>(style, modw, bias);
    prep_w<<<1024, 256>>>(weight);
    prep_gain<<<dim3(16, 8), 256>>>();
    prep_xt<<<dim3(64, 8, 16), 256>>>(x);
    conv_main<<<512, NTHREADS, SMEM_TOTAL>>>(out);
}

// round 6
// speedup vs baseline: 1.0112x; 1.0112x over previous
#include <cuda_runtime.h>
#include <cuda_fp16.h>
#include <cstdint>

// ============================================================================
// ModulatedConv1d (B=16, C=512, L=2048, K=3, pad=1) — plain sm_100 path
//   s[b,i]    = MOD_SCALE * style[b,:] @ modW[i,:] + bias[i]
//   gain[b,o] = SCALE * rsqrt(SCALE^2 * sum_i s^2 * wsq[o,i] + 1e-8)
//   out[b,o,l]= gain[b,o] * sum_{i,k} W[o,i,k] * s[b,i] * x[b,i,l+k-1]
// Preps emit chunk-major, PRE-SWIZZLED gmem images of W (g_w2) and s*x (g_x2).
// Main loop feeds SMEM with ONE cp.async.bulk per operand per K-chunk
// (mbarrier complete_tx), ldmatrix fragments, mma.m16n8k16 f16->f32.
// CTA tile 128(o) x 256(l), 512 threads, 4-stage ring.
// ============================================================================

#define MOD_SCALE_F 0.04419417382415922f   /* 1/sqrt(512)   */
#define SCALE_F     0.014731391274719739f  /* 1/sqrt(512*9) */

#define NTHREADS 512
// Stage: A = 3 taps x 128 rows x 64B = 24576 ; X = 258 rows x 64B = 16512
#define A_TAP   8192
#define X_OFF   24576
#define STAGE   41088
#define NSTAGE  4
#define MBAR_SZ 64
#define SMEM_TOTAL (MBAR_SZ + NSTAGE * STAGE)   /* 164416 */

// static device scratch (no runtime allocation)
__device__ float  g_s[16 * 512];
__device__ float  g_wsq[512 * 512];
__device__ float  g_gain[16 * 512];
// W chunk-major: [ic(16)][otile(4)][tap(3)][o(128)][c'(4) x 8 halves]
__device__ __half g_w2[16 * 4 * 3 * 128 * 32];
// X chunk-major: [b(16)][ic(16)][R(2056)][c'(4) x 8 halves],  R = l + 1
__device__ __half g_x2[(size_t)16 * 16 * 2056 * 32];

// ---------------------------------------------------------------------------
__device__ __forceinline__ uint32_t smem_u32(const void* p) {
    uint32_t a;
    asm("{ .reg .u64 t; cvta.to.shared.u64 t, %1; cvt.u32.u64 %0, t; }" : "=r"(a) : "l"(p));
    return a;
}
__device__ __forceinline__ void bulk_cp(uint32_t dst, const void* src, uint32_t bytes,
                                        uint32_t mbar) {
    asm volatile(
        "cp.async.bulk.shared::cluster.global.mbarrier::complete_tx::bytes "
        "[%0], [%1], %2, [%3];"
        :: "r"(dst), "l"(src), "r"(bytes), "r"(mbar) : "memory");
}
__device__ __forceinline__ void mbar_init(uint32_t mbar, uint32_t cnt) {
    asm volatile("mbarrier.init.shared.b64 [%0], %1;" :: "r"(mbar), "r"(cnt) : "memory");
}
__device__ __forceinline__ void mbar_expect_tx(uint32_t mbar, uint32_t tx) {
    asm volatile("mbarrier.arrive.expect_tx.shared.b64 _, [%0], %1;"
                 :: "r"(mbar), "r"(tx) : "memory");
}
__device__ __forceinline__ void mbar_wait(uint32_t mbar, uint32_t parity) {
    uint32_t done;
    asm volatile("{\n\t.reg .pred p;\n\t"
        "mbarrier.try_wait.parity.acquire.cta.shared::cta.b64 p, [%1], %2;\n\t"
        "selp.b32 %0, 1, 0, p;\n\t}" : "=r"(done) : "r"(mbar), "r"(parity) : "memory");
    if (!done) {
        asm volatile("{\n\t.reg .pred P1;\n\t"
            "WAIT_LOOP_%=:\n\t"
            "mbarrier.try_wait.parity.acquire.cta.shared::cta.b64 P1, [%0], %1, 0x989680;\n\t"
            "@P1 bra.uni WAIT_DONE_%=;\n\t"
            "bra.uni WAIT_LOOP_%=;\n\t"
            "WAIT_DONE_%=:\n\t}" :: "r"(mbar), "r"(parity) : "memory");
    }
}
__device__ __forceinline__ void ldsm4(uint32_t* r, uint32_t addr) {
    asm volatile("ldmatrix.sync.aligned.m8n8.x4.shared.b16 {%0,%1,%2,%3}, [%4];"
        : "=r"(r[0]), "=r"(r[1]), "=r"(r[2]), "=r"(r[3]) : "r"(addr));
}
__device__ __forceinline__ void mma_f16(float* c, const uint32_t* a, uint32_t b0, uint32_t b1) {
    asm volatile(
        "mma.sync.aligned.m16n8k16.row.col.f32.f16.f16.f32 "
        "{%0,%1,%2,%3}, {%4,%5,%6,%7}, {%8,%9}, {%0,%1,%2,%3};"
        : "+f"(c[0]), "+f"(c[1]), "+f"(c[2]), "+f"(c[3])
        : "r"(a[0]), "r"(a[1]), "r"(a[2]), "r"(a[3]), "r"(b0), "r"(b1));
}

// ---------------------------------------------------------------------------
// Prep kernels
// ---------------------------------------------------------------------------
__global__ void prep_w(const float* __restrict__ w) {
    int idx = blockIdx.x * 256 + threadIdx.x;   // grid 1024: idx = o*512 + i
    int o = idx >> 9, i = idx & 511;
    float w0 = w[idx * 3 + 0];
    float w1 = w[idx * 3 + 1];
    float w2 = w[idx * 3 + 2];
    g_wsq[idx] = w0 * w0 + w1 * w1 + w2 * w2;

    int ic = i >> 5, c = (i >> 3) & 3, h = i & 7;
    int otile = o >> 7, o128 = o & 127;
    int cp = c ^ ((o128 >> 1) & 3);
    size_t base = ((size_t)((ic * 4 + otile) * 3) * 128 + o128) * 32 + cp * 8 + h;
    // tap stride in halves: 128*32 = 4096
    g_w2[base + 0 * 4096] = __float2half_rn(w0);
    g_w2[base + 1 * 4096] = __float2half_rn(w1);
    g_w2[base + 2 * 4096] = __float2half_rn(w2);
}

__global__ void prep_s(const float* __restrict__ style, const float* __restrict__ modw,
                       const float* __restrict__ bias) {
    __shared__ float st[512];
    int b = blockIdx.x, chunk = blockIdx.y;  // grid (16, 8)
    for (int i = threadIdx.x; i < 512; i += 256) st[i] = style[b * 512 + i];
    __syncthreads();
    int warp = threadIdx.x >> 5, lane = threadIdx.x & 31;
    for (int it = 0; it < 8; it++) {
        int i = chunk * 64 + it * 8 + warp;
        const float* mrow = modw + (size_t)i * 512;
        float acc = 0.f;
        #pragma unroll
        for (int t = 0; t < 16; t++) acc += mrow[lane + t * 32] * st[lane + t * 32];
        #pragma unroll
        for (int o = 16; o; o >>= 1) acc += __shfl_xor_sync(0xFFFFFFFFu, acc, o);
        if (lane == 0) g_s[b * 512 + i] = acc * MOD_SCALE_F + bias[i];
    }
}

__global__ void prep_gain() {
    __shared__ float s2[512];
    int b = blockIdx.x, chunk = blockIdx.y;  // grid (16, 8)
    for (int i = threadIdx.x; i < 512; i += 256) {
        float v = g_s[b * 512 + i];
        s2[i] = v * v;
    }
    __syncthreads();
    int warp = threadIdx.x >> 5, lane = threadIdx.x & 31;
    for (int it = 0; it < 8; it++) {
        int o = chunk * 64 + it * 8 + warp;
        const float* wr = g_wsq + (size_t)o * 512;
        float acc = 0.f;
        #pragma unroll
        for (int t = 0; t < 16; t++) acc += wr[lane + t * 32] * s2[lane + t * 32];
        #pragma unroll
        for (int off = 16; off; off >>= 1) acc += __shfl_xor_sync(0xFFFFFFFFu, acc, off);
        if (lane == 0)
            g_gain[b * 512 + o] = SCALE_F * rsqrtf(SCALE_F * SCALE_F * acc + 1e-8f);
    }
}

// zero boundary rows R in {0} u [2049, 2056) for every (b, ic)
__global__ void prep_xzero() {
    int b = blockIdx.x, ic = blockIdx.y;     // grid (16,16), 256 threads
    int ridx = threadIdx.x >> 5;             // 0..7
    int col  = threadIdx.x & 31;
    int R = (ridx == 0) ? 0 : (2048 + ridx);
    g_x2[((size_t)(b * 16 + ic) * 2056 + R) * 32 + col] = __float2half_rn(0.f);
}

// Transpose + scale + fp16 into swizzled chunk-major layout.
// x[b][i][l] -> g_x2[b][i>>5][l+1][swz 16B units]
__global__ void prep_xt(const float* __restrict__ x) {
    __shared__ float sm[64][33];
    const int lt = blockIdx.x;   // 0..63
    const int it = blockIdx.y;   // 0..7
    const int b  = blockIdx.z;   // 0..15
    const int warp = threadIdx.x >> 5, lane = threadIdx.x & 31;
    const int l0 = lt * 32, i0 = it * 64;
    const float* xb = x + ((size_t)b * 512) * 2048;

    #pragma unroll
    for (int r = 0; r < 8; r++) {
        int il = warp * 8 + r;
        float sv = g_s[b * 512 + i0 + il];
        sm[il][lane] = xb[(size_t)(i0 + il) * 2048 + l0 + lane] * sv;
    }
    __syncthreads();
    #pragma unroll
    for (int rr = 0; rr < 4; rr++) {
        int ll = warp * 4 + rr;
        int l = l0 + ll;
        int R = l + 1;
        __half2 h = __floats2half2_rn(sm[lane * 2][ll], sm[lane * 2 + 1][ll]);
        int i = i0 + lane * 2;
        int ic = i >> 5, c = (i >> 3) & 3, hh = i & 7;
        int cp = c ^ ((R >> 1) & 3);
        *(__half2*)(g_x2 + ((size_t)(b * 16 + ic) * 2056 + R) * 32 + cp * 8 + hh) = h;
    }
}

// ---------------------------------------------------------------------------
// Main kernel: 512 CTAs = 4 o x 8 l x 16 b; 512 threads (16 warps, 4m x 4n)
// warp tile 32(o) x 64(l); 16 K-chunks of 32 i x 3 taps; 4-stage bulk ring.
// ---------------------------------------------------------------------------
__global__ void __launch_bounds__(NTHREADS, 1)
conv_main(float* __restrict__ out) {
    extern __shared__ char smem[];
    const uint32_t sb = smem_u32(smem);

    const int tid  = threadIdx.x;
    const int warp = tid >> 5;
    const int lane = tid & 31;
    const int mw = (warp & 3) * 32;
    const int nw = (warp >> 2) * 64;

    const int bx    = blockIdx.x;
    const int otile = bx & 3;
    const int obase = otile * 128;
    const int l0    = ((bx >> 2) & 7) * 256;
    const int b     = bx >> 5;

    // per-lane fragment geometry (mapping identical to R4/R5; swizzled 64B rows)
    const int rowA = mw + (lane & 15);
    const uint32_t swa = (uint32_t)((rowA >> 1) & 3);
    const uint32_t cA  = (uint32_t)((lane >> 4) & 1);
    const uint32_t aAddr = (uint32_t)rowA * 64;
    const int rowB = nw + (lane & 7) + ((lane >> 4) << 3);
    const uint32_t cB = (uint32_t)((lane >> 3) & 1);
    uint32_t swb[3];
    #pragma unroll
    for (int t = 0; t < 3; t++) swb[t] = (uint32_t)(((rowB + t) >> 1) & 3);

    const __half* wsrc_base = g_w2 + (size_t)otile * 12288;   // + ic*4*12288
    const __half* xsrc_base = g_x2 + ((size_t)b * 16 * 2056 + l0) * 32;

    float acc[2][8][4];
    #pragma unroll
    for (int mi = 0; mi < 2; mi++)
        #pragma unroll
        for (int ni = 0; ni < 8; ni++)
            #pragma unroll
            for (int j = 0; j < 4; j++) acc[mi][ni][j] = 0.f;

    if (tid == 0) {
        #pragma unroll
        for (int s = 0; s < NSTAGE; s++) mbar_init(sb + s * 8, 1);
    }
    __syncthreads();

    auto issue = [&](int ic) {
        uint32_t st = sb + MBAR_SZ + (uint32_t)(ic & (NSTAGE - 1)) * STAGE;
        uint32_t mb = sb + (uint32_t)(ic & (NSTAGE - 1)) * 8;
        mbar_expect_tx(mb, STAGE);
        bulk_cp(st,         wsrc_base + (size_t)ic * 4 * 12288, 24576, mb);
        bulk_cp(st + X_OFF, xsrc_base + (size_t)ic * 2056 * 32, 16512, mb);
    };

    if (tid == 0) { issue(0); issue(1); issue(2); }

    for (int ic = 0; ic < 16; ic++) {
        mbar_wait(sb + (uint32_t)(ic & (NSTAGE - 1)) * 8, (uint32_t)((ic >> 2) & 1));

        const uint32_t base = sb + MBAR_SZ + (uint32_t)(ic & (NSTAGE - 1)) * STAGE;

        #pragma unroll
        for (int t = 0; t < 3; t++) {
            #pragma unroll
            for (int ks = 0; ks < 2; ks++) {
                uint32_t a0[4], a1[4];
                uint32_t aadr = base + t * A_TAP + aAddr
                              + (((uint32_t)(ks * 2) + cA) ^ swa) * 16;
                ldsm4(a0, aadr);
                ldsm4(a1, aadr + 16 * 64);
                #pragma unroll
                for (int np = 0; np < 4; np++) {
                    uint32_t bf[4];
                    uint32_t badr = base + X_OFF + (uint32_t)(rowB + np * 16 + t) * 64
                                  + (((uint32_t)(ks * 2) + cB) ^ swb[t]) * 16;
                    ldsm4(bf, badr);
                    mma_f16(acc[0][np * 2],     a0, bf[0], bf[1]);
                    mma_f16(acc[1][np * 2],     a1, bf[0], bf[1]);
                    mma_f16(acc[0][np * 2 + 1], a0, bf[2], bf[3]);
                    mma_f16(acc[1][np * 2 + 1], a1, bf[2], bf[3]);
                }
            }
        }

        __syncthreads();
        if (tid == 0 && ic < 13) issue(ic + 3);
    }

    // ---- epilogue: apply gain, store ----
    {
        const int r0 = obase + mw + (lane >> 2);
        const float g00 = g_gain[b * 512 + r0];
        const float g01 = g_gain[b * 512 + r0 + 8];
        const float g10 = g_gain[b * 512 + r0 + 16];
        const float g11 = g_gain[b * 512 + r0 + 24];
        const int lcol = l0 + nw + (lane & 3) * 2;

        #pragma unroll
        for (int mi = 0; mi < 2; mi++) {
            const int ra = r0 + mi * 16;
            const float ga = mi ? g10 : g00;
            const float gb = mi ? g11 : g01;
            float* outa = out + ((size_t)(b * 512 + ra)) * 2048 + lcol;
            float* outb = out + ((size_t)(b * 512 + ra + 8)) * 2048 + lcol;
            #pragma unroll
            for (int ni = 0; ni < 8; ni++) {
                float2 va, vb;
                va.x = acc[mi][ni][0] * ga;
                va.y = acc[mi][ni][1] * ga;
                vb.x = acc[mi][ni][2] * gb;
                vb.y = acc[mi][ni][3] * gb;
                *(float2*)(outa + ni * 8) = va;
                *(float2*)(outb + ni * 8) = vb;
            }
        }
    }
}

// ---------------------------------------------------------------------------
extern "C" void kernel_launch(void* const* d_in, const int* in_sizes, int n_in,
                              void* d_out, int out_size) {
    const float* x      = (const float*)d_in[0];
    const float* style  = (const float*)d_in[1];
    const float* weight = (const float*)d_in[2];
    const float* modw   = (const float*)d_in[3];
    const float* bias   = (const float*)d_in[4];
    float* out = (float*)d_out;

    cudaFuncSetAttribute(conv_main, cudaFuncAttributeMaxDynamicSharedMemorySize, SMEM_TOTAL);

    prep_s<<<dim3(16, 8), 256>>>(style, modw, bias);
    prep_w<<<1024, 256>>>(weight);
    prep_gain<<<dim3(16, 8), 256>>>();
    prep_xzero<<<dim3(16, 16), 256>>>();
    prep_xt<<<dim3(64, 8, 16), 256>>>(x);
    conv_main<<<512, NTHREADS, SMEM_TOTAL>>>(out);
}